// round 6
// baseline (speedup 1.0000x reference)
#include <cuda_runtime.h>
#include <cstdint>

#define B        8
#define NPOS     4096
#define CHUNK    32
#define NCHUNK   128
#define PTS      256
#define OUT_DIM  1024
#define IN_DIM   1024
#define EPS      1e-6f
#define ROWP     36      // sprops row stride (floats): conflict-free for LDS/STS.128
#define NL2E_H   (-0.72134752044448170367f)   // -0.5 * log2(e)

// triangular (i, j<i) warp-pair blocks for the balanced dup scan
__constant__ unsigned char PI[28] = {1,2,2,3,3,3,4,4,4,4,5,5,5,5,5,6,6,6,6,6,6,7,7,7,7,7,7,7};
__constant__ unsigned char PJ[28] = {0,0,1,0,1,2,0,1,2,3,0,1,2,3,4,0,1,2,3,4,5,0,1,2,3,4,5,6};

// ---------------------------------------------------------------------------
// packed f32x2 helpers (FFMA2/FADD2/FMUL2 via PTX)
// ---------------------------------------------------------------------------
__device__ __forceinline__ uint64_t PK(float x, float y) {
    uint64_t r; asm("mov.b64 %0, {%1, %2};" : "=l"(r) : "f"(x), "f"(y)); return r;
}
__device__ __forceinline__ float2 UPK(uint64_t v) {
    float lo, hi; asm("mov.b64 {%0, %1}, %2;" : "=f"(lo), "=f"(hi) : "l"(v));
    return make_float2(lo, hi);
}
__device__ __forceinline__ uint64_t ADD2(uint64_t a, uint64_t b) {
    uint64_t r; asm("add.rn.f32x2 %0, %1, %2;" : "=l"(r) : "l"(a), "l"(b)); return r;
}
__device__ __forceinline__ uint64_t MUL2(uint64_t a, uint64_t b) {
    uint64_t r; asm("mul.rn.f32x2 %0, %1, %2;" : "=l"(r) : "l"(a), "l"(b)); return r;
}
__device__ __forceinline__ uint64_t FMA2(uint64_t a, uint64_t b, uint64_t c) {
    uint64_t r; asm("fma.rn.f32x2 %0, %1, %2, %3;" : "=l"(r) : "l"(a), "l"(b), "l"(c)); return r;
}
__device__ __forceinline__ float ex2(float x) {
    float r; asm("ex2.approx.f32 %0, %1;" : "=f"(r) : "f"(x)); return r;
}

// ---------------------------------------------------------------------------
// Threefry-2x32, 20 rounds
// ---------------------------------------------------------------------------
__host__ __device__ __forceinline__ void tf2x32(uint32_t k0, uint32_t k1,
                                                uint32_t c0, uint32_t c1,
                                                uint32_t& o0, uint32_t& o1) {
    uint32_t ks2 = k0 ^ k1 ^ 0x1BD11BDAu;
    uint32_t x0 = c0 + k0, x1 = c1 + k1;
#define TF_ROUND(r) { x0 += x1; x1 = (x1 << (r)) | (x1 >> (32 - (r))); x1 ^= x0; }
    TF_ROUND(13) TF_ROUND(15) TF_ROUND(26) TF_ROUND(6)
    x0 += k1;  x1 += ks2 + 1u;
    TF_ROUND(17) TF_ROUND(29) TF_ROUND(16) TF_ROUND(24)
    x0 += ks2; x1 += k0 + 2u;
    TF_ROUND(13) TF_ROUND(15) TF_ROUND(26) TF_ROUND(6)
    x0 += k0;  x1 += k1 + 3u;
    TF_ROUND(17) TF_ROUND(29) TF_ROUND(16) TF_ROUND(24)
    x0 += k1;  x1 += ks2 + 4u;
    TF_ROUND(13) TF_ROUND(15) TF_ROUND(26) TF_ROUND(6)
    x0 += ks2; x1 += k0 + 5u;
#undef TF_ROUND
    o0 = x0; o1 = x1;
}

__device__ __forceinline__ uint32_t rand_bits_part(uint32_t k0, uint32_t k1,
                                                   uint32_t e) {
    uint32_t o0, o1;
    tf2x32(k0, k1, 0u, e, o0, o1);
    return o0 ^ o1;
}

__device__ __forceinline__ float u01(uint32_t bits) {
    return __uint_as_float((bits >> 9) | 0x3F800000u) - 1.0f;
}

// ---------------------------------------------------------------------------
__global__ void sl_init_kernel(const float* __restrict__ bias,
                               float* __restrict__ y) {
    int i = blockIdx.x * blockDim.x + threadIdx.x;
    if (i < B * OUT_DIM) y[i] = bias[i & (OUT_DIM - 1)];
}

// ---------------------------------------------------------------------------
// One block per (chunk, batch); 256 threads = 256 candidate points.
// ---------------------------------------------------------------------------
__global__ __launch_bounds__(256, 5) void sl_chunk_kernel(
    const float* __restrict__ x,
    const float* __restrict__ means,
    const float* __restrict__ sigmas,
    const float* __restrict__ values,
    float* __restrict__ y,
    uint32_t kg0, uint32_t kg1, uint32_t kl0, uint32_t kl1)
{
    // pair-packed gaussian params (16 pairs):
    //   sA[p] = (-m0_{2p}, -m0_{2p+1}, -m1_{2p}, -m1_{2p+1})
    //   sB[p] = ( z_{2p},   z_{2p+1},   w_{2p},   w_{2p+1}), z/w = NL2E_H/(eps+sig)
    __shared__ __align__(16) float4 sA[CHUNK / 2];
    __shared__ __align__(16) float4 sB[CHUNK / 2];
    __shared__ float2 smn[CHUNK];              // positive means for codegen
    __shared__ float  sval[CHUNK];
    __shared__ __align__(16) int   scode[PTS];
    __shared__ __align__(16) float sprops[PTS][ROWP];
    __shared__ __align__(16) float2 spart2[16][16];
    __shared__ __align__(16) float  svv[CHUNK];
    __shared__ unsigned sdup[8];

    const int tid   = threadIdx.x;
    const int cc    = blockIdx.x;
    const int bb    = blockIdx.y;
    const int k     = tid >> 3;
    const int which = tid & 7;
    const int lane  = tid & 31;
    const int warp  = tid >> 5;

    if (tid < 8) sdup[tid] = 0u;
    if (tid < CHUNK) {
        int pos = bb * NPOS + cc * CHUNK + tid;
        float2 mm = ((const float2*)means)[pos];
        float2 ss = ((const float2*)sigmas)[pos];
        smn[tid]  = mm;
        sval[tid] = values[pos];
        int p = tid >> 1, h = tid & 1;
        float* a = (float*)&sA[p];
        float* b = (float*)&sB[p];
        a[h]     = -mm.x;
        a[2 + h] = -mm.y;
        b[h]     = NL2E_H / (EPS + ss.x);
        b[2 + h] = NL2E_H / (EPS + ss.y);
    }
    __syncthreads();

    const float2 mk = smn[k];
    const float m0 = mk.x, m1 = mk.y;
    int o, j;

    if (which < 4) {
        // FLOOR_MASK rows: (T,T),(T,F),(F,T),(F,F); True -> floor
        float f0 = (which < 2)        ? floorf(m0) : ceilf(m0);
        float f1 = ((which & 1) == 0) ? floorf(m1) : ceilf(m1);
        o = (int)f0;
        j = (int)f1;
    } else {
        // global (which 4,5) / local (which 6,7) share element index; key differs
        bool isg = (which < 6);
        uint32_t e  = (uint32_t)(bb * 16384 + cc * 128 + k * 4 + (which & 1) * 2);
        uint32_t key0 = isg ? kg0 : kl0;
        uint32_t key1 = isg ? kg1 : kl1;
        float u0 = u01(rand_bits_part(key0, key1, e));
        float u1 = u01(rand_bits_part(key0, key1, e + 1));
        float lu0 = __fmul_rn(u0, 1.0f - EPS);
        float lu1 = __fmul_rn(u1, 1.0f - EPS);
        if (isg) {
            o = (int)floorf(__fmul_rn(lu0, 1024.0f));
            j = (int)floorf(__fmul_rn(lu1, 1024.0f));
        } else {
            float mn0 = rintf(m0), mn1 = rintf(m1);
            float lo0 = mn0 - 8.0f, lo1 = mn1 - 8.0f;
            if (lo0 < 0.0f) lo0 = 0.0f;
            if (mn0 + 8.0f > 1024.0f) lo0 = 1008.0f;
            if (lo1 < 0.0f) lo1 = 0.0f;
            if (mn1 + 8.0f > 1024.0f) lo1 = 1008.0f;
            o = (int)__fadd_rn(__fmul_rn(lu0, 16.0f), lo0);
            j = (int)__fadd_rn(__fmul_rn(lu1, 16.0f), lo1);
        }
    }

    const int code = o * IN_DIM + j;
    // intra-warp duplicate mask (register-only, no smem needed)
    unsigned mm_any = __match_any_sync(0xffffffffu, code);
    const bool intra = (mm_any & ((1u << lane) - 1u)) != 0u;
    scode[tid] = code;
    __syncthreads();

    // balanced cross-warp dup scan: 28 (i,j) blocks round-robin over 8 warps
    for (int t = warp; t < 28; t += 8) {
        int pi = PI[t], pjw = PJ[t];
        int ti = scode[pi * 32 + lane];
        const int4* c4 = (const int4*)&scode[pjw * 32];
        bool d = false;
        #pragma unroll
        for (int u = 0; u < 8; u++) {
            int4 c = c4[u];
            d = d | (c.x == ti) | (c.y == ti) | (c.z == ti) | (c.w == ti);
        }
        unsigned bal = __ballot_sync(0xffffffffu, d);
        if (lane == 0 && bal) atomicOr(&sdup[pi], bal);
    }
    __syncthreads();

    const bool dup = intra || ((sdup[warp] >> lane) & 1u);

    // packed density rows: 2 gaussian-pairs (4 props) per iter, STS.128
    const float po = (float)o, pj = (float)j;
    const float zm = dup ? 0.0f : 1.0f;
    const uint64_t po2 = PK(po, po), pj2 = PK(pj, pj), zm2 = PK(zm, zm);
    #pragma unroll
    for (int p = 0; p < CHUNK / 2; p += 2) {
        float2 res[2];
        #pragma unroll
        for (int h = 0; h < 2; h++) {
            float4 A  = sA[p + h];
            float4 Bv = sB[p + h];
            uint64_t d0 = ADD2(po2, PK(A.x, A.y));
            uint64_t d1 = ADD2(pj2, PK(A.z, A.w));
            uint64_t s  = MUL2(MUL2(d0, d0), PK(Bv.x, Bv.y));
            s = FMA2(MUL2(d1, d1), PK(Bv.z, Bv.w), s);
            float2 sf = UPK(s);
            res[h] = UPK(MUL2(zm2, PK(ex2(sf.x), ex2(sf.y))));
        }
        *(float4*)&sprops[tid][p * 2] =
            make_float4(res[0].x, res[0].y, res[1].x, res[1].y);
    }
    __syncthreads();

    // packed column sums: stage 1 = 16 row-groups x 16 col-pairs
    {
        int rg = tid >> 4, cp = tid & 15;
        int r0 = rg * 16;
        uint64_t acc = PK(0.0f, 0.0f);
        #pragma unroll
        for (int r = 0; r < 16; r++) {
            float2 v = *(const float2*)&sprops[r0 + r][cp * 2];
            acc = ADD2(acc, PK(v.x, v.y));
        }
        spart2[rg][cp] = UPK(acc);
    }
    __syncthreads();
    if (tid < CHUNK) {
        const float* sp = (const float*)spart2;
        float s = 0.0f;
        #pragma unroll
        for (int rg = 0; rg < 16; rg++) s += sp[rg * 32 + tid];
        svv[tid] = sval[tid] / s;
    }
    __syncthreads();

    if (!dup) {
        const float4* row = (const float4*)&sprops[tid][0];
        const float4* vv4 = (const float4*)svv;
        uint64_t acc = PK(0.0f, 0.0f);
        #pragma unroll
        for (int q = 0; q < CHUNK / 4; q++) {
            float4 p = row[q];
            float4 w = vv4[q];
            acc = FMA2(PK(p.x, p.y), PK(w.x, w.y), acc);
            acc = FMA2(PK(p.z, p.w), PK(w.z, w.w), acc);
        }
        float2 a = UPK(acc);
        float contrib = (a.x + a.y) * x[bb * IN_DIM + j];
        atomicAdd(&y[bb * OUT_DIM + o], contrib);
    }
}

// ---------------------------------------------------------------------------
extern "C" void kernel_launch(void* const* d_in, const int* in_sizes, int n_in,
                              void* d_out, int out_size) {
    const float* x      = (const float*)d_in[0];
    const float* means  = (const float*)d_in[1];
    const float* sigmas = (const float*)d_in[2];
    const float* values = (const float*)d_in[3];
    const float* bias   = (const float*)d_in[4];
    float* y = (float*)d_out;

    // harmless if unsupported; asks for the full 228KB smem carveout
    (void)cudaFuncSetAttribute(sl_chunk_kernel,
                               cudaFuncAttributePreferredSharedMemoryCarveout, 100);

    // key(42) = (0,42); partitionable split: child i = threefry(key, (0,i))
    uint32_t kg0, kg1, kl0, kl1;
    tf2x32(0u, 42u, 0u, 0u, kg0, kg1);
    tf2x32(0u, 42u, 0u, 1u, kl0, kl1);

    sl_init_kernel<<<(B * OUT_DIM + 255) / 256, 256>>>(bias, y);

    dim3 grid(NCHUNK, B);
    sl_chunk_kernel<<<grid, 256>>>(x, means, sigmas, values, y,
                                   kg0, kg1, kl0, kl1);
}